// round 2
// baseline (speedup 1.0000x reference)
#include <cuda_runtime.h>
#include <cstdint>

// Problem constants
#define BATCHN 128
#define GS 7
#define NB 2
#define NC 20
#define CH 30                         // 2*4 + 2 + 20
#define CELLS (BATCHN * GS * GS)      // 6272
#define NTOT (CELLS * NB)             // 12544
#define NPOW 16384
#define PER_BATCH (GS * GS * NB)      // 98
#define THR_NMS 0.3f

// ---------------- device scratch (static allocation; no cudaMalloc) ----------
__device__ unsigned long long g_keys[NTOT];
__device__ unsigned long long g_sorted[NTOT];
__device__ float4 g_box[NTOT];
__device__ float g_score[NTOT];
__device__ unsigned char g_label[NTOT];
__device__ unsigned char g_valid[NTOT];

// sigmoid matching XLA-GPU exp-based logistic expansion:
// 1/(1+__nv_expf(-x)) with IEEE (div.rn) division.
__device__ __forceinline__ float sigmoidf(float x) {
    return 1.0f / (1.0f + expf(-x));
}

// float -> order-preserving uint32 (monotone for all finite + infinities)
__device__ __forceinline__ unsigned f2sortable(float f) {
    unsigned b = __float_as_uint(f);
    return (b & 0x80000000u) ? ~b : (b | 0x80000000u);
}

// ---------------- 1) decode ------------------------------------------------
__global__ void decode_kernel(const float* __restrict__ p) {
    int cell = blockIdx.x * blockDim.x + threadIdx.x;
    if (cell >= CELLS) return;
    const float* q = p + (size_t)cell * CH;
    int rem = cell % (GS * GS);
    int gy = rem / GS;
    int gx = rem % GS;

    // label = argmax over sigmoid(cls) + 1 (first max wins, like jnp.argmax)
    float best = sigmoidf(q[8 + NB + 0]);
    int bi = 0;
#pragma unroll
    for (int c = 1; c < NC; c++) {
        float v = sigmoidf(q[8 + NB + c]);
        if (v > best) { best = v; bi = c; }
    }
    unsigned char lab = (unsigned char)(bi + 1);

#pragma unroll
    for (int bb = 0; bb < NB; bb++) {
        int n = cell * NB + bb;
        float conf = sigmoidf(q[8 + bb]);
        bool valid = conf > 0.5f;
        float sx = sigmoidf(q[bb * 4 + 0]);
        float sy = sigmoidf(q[bb * 4 + 1]);
        float w = q[bb * 4 + 2];
        float h = q[bb * 4 + 3];
        float cx = (sx + (float)gx) / 7.0f;
        float cy = (sy + (float)gy) / 7.0f;
        float4 bx;
        bx.x = cx - w / 2.0f;
        bx.y = cy - h / 2.0f;
        bx.z = cx + w / 2.0f;
        bx.w = cy + h / 2.0f;
        g_box[n] = bx;
        g_score[n] = conf;
        g_label[n] = lab;
        g_valid[n] = valid ? 1 : 0;
        float keyf = valid ? conf : __int_as_float(0xff800000); // -inf for invalid
        unsigned kb = f2sortable(keyf);
        // descending sort on (score, idx): stable-argsort-reversed semantics
        g_keys[n] = ((unsigned long long)kb << 32) | (unsigned)n;
    }
}

// ---------------- 2) single-CTA bitonic sort (descending, 64-bit keys) ------
__global__ void sort_kernel() {
    extern __shared__ unsigned long long sk[];
    int tid = threadIdx.x;
    for (int i = tid; i < NPOW; i += blockDim.x)
        sk[i] = (i < NTOT) ? g_keys[i] : 0ULL;   // pad sorts to very end
    __syncthreads();

    for (unsigned k = 2; k <= NPOW; k <<= 1) {
        for (unsigned j = k >> 1; j >= 1; j >>= 1) {
            for (unsigned t = tid; t < (NPOW >> 1); t += blockDim.x) {
                unsigned i = ((t & ~(j - 1u)) << 1) | (t & (j - 1u));
                unsigned partner = i | j;
                unsigned long long a = sk[i];
                unsigned long long b = sk[partner];
                bool dir = ((i & k) == 0);       // descending segment
                if ((a < b) == dir) { sk[i] = b; sk[partner] = a; }
            }
            __syncthreads();
        }
    }
    for (int i = tid; i < NTOT; i += blockDim.x)
        g_sorted[i] = sk[i];
}

// ---------------- 3) write outputs (keep defaults to 0) ---------------------
// layout: [ids (N)] [boxes (N,4)] [labels (N)] [scores (N)] [keep (N)]
__global__ void write_kernel(float* __restrict__ out) {
    int p = blockIdx.x * blockDim.x + threadIdx.x;
    if (p >= NTOT) return;
    unsigned idx = (unsigned)(g_sorted[p] & 0xffffffffu);
    out[p] = (float)(idx / PER_BATCH);
    float4 bx = g_box[idx];
    float* ob = out + NTOT + 4 * p;
    ob[0] = bx.x; ob[1] = bx.y; ob[2] = bx.z; ob[3] = bx.w;
    out[5 * NTOT + p] = (float)g_label[idx];
    out[6 * NTOT + p] = g_score[idx];
    out[7 * NTOT + p] = 0.0f;
}

// ---------------- 4) per-batch greedy NMS (1 warp per batch) ----------------
__global__ void nms_kernel(float* __restrict__ out) {
    __shared__ float4 s_box[PER_BATCH];
    __shared__ short s_pos[PER_BATCH];
    __shared__ unsigned char s_lab[PER_BATCH];
    __shared__ unsigned char s_sup[PER_BATCH];

    int lane = threadIdx.x;
    unsigned myb = blockIdx.x;
    int cnt = 0;

    // Ordered compaction of this batch's valid boxes from the sorted prefix.
    // All valid entries precede all invalid ones (invalid keys are -inf),
    // so stop at the first invalid.
    for (int base = 0; base < NTOT; base += 32) {
        int pp = base + lane;
        unsigned idx = 0;
        bool v = false;
        if (pp < NTOT) {
            idx = (unsigned)(g_sorted[pp] & 0xffffffffu);
            v = (g_valid[idx] != 0);
        }
        bool mine = v && (idx / PER_BATCH == myb);
        unsigned m = __ballot_sync(0xffffffffu, mine);
        if (mine) {
            int off = cnt + __popc(m & ((1u << lane) - 1u));
            s_box[off] = g_box[idx];
            s_pos[off] = (short)pp;
            s_lab[off] = g_label[idx];
        }
        cnt += __popc(m);
        unsigned anyinv = __ballot_sync(0xffffffffu, (pp < NTOT) && !v);
        if (anyinv) break;
    }
    __syncwarp();
    for (int i = lane; i < cnt; i += 32) s_sup[i] = 0;
    __syncwarp();

    // Greedy NMS: serial over i (score-descending), parallel over j.
    for (int i = 0; i < cnt; i++) {
        if (s_sup[i]) continue;                      // uniform (shared) branch
        float4 bi = s_box[i];
        int li = s_lab[i];
        float ai = (bi.z - bi.x) * (bi.w - bi.y);
        for (int j = i + 1 + lane; j < cnt; j += 32) {
            if (s_sup[j] || s_lab[j] != li) continue;
            float4 bj = s_box[j];
            float ltx = fmaxf(bi.x, bj.x);
            float lty = fmaxf(bi.y, bj.y);
            float rbx = fminf(bi.z, bj.z);
            float rby = fminf(bi.w, bj.w);
            float iw = fmaxf(rbx - ltx, 0.0f);
            float ih = fmaxf(rby - lty, 0.0f);
            float inter = iw * ih;
            float aj = (bj.z - bj.x) * (bj.w - bj.y);
            float uni = ai + aj - inter;
            float iou = inter / fmaxf(uni, 1e-9f);
            if (iou > THR_NMS) s_sup[j] = 1;
        }
        __syncwarp();
    }

    for (int i = lane; i < cnt; i += 32)
        if (!s_sup[i]) out[7 * NTOT + (int)s_pos[i]] = 1.0f;
}

// ---------------- launch -----------------------------------------------------
extern "C" void kernel_launch(void* const* d_in, const int* in_sizes, int n_in,
                              void* d_out, int out_size) {
    const float* p = (const float*)d_in[0];
    float* out = (float*)d_out;

    cudaFuncSetAttribute(sort_kernel,
                         cudaFuncAttributeMaxDynamicSharedMemorySize,
                         NPOW * (int)sizeof(unsigned long long));

    decode_kernel<<<(CELLS + 127) / 128, 128>>>(p);
    sort_kernel<<<1, 1024, NPOW * sizeof(unsigned long long)>>>();
    write_kernel<<<(NTOT + 255) / 256, 256>>>(out);
    nms_kernel<<<BATCHN, 32>>>(out);
}

// round 3
// speedup vs baseline: 1.1594x; 1.1594x over previous
#include <cuda_runtime.h>
#include <cstdint>

// Problem constants
#define BATCHN 128
#define GS 7
#define NB 2
#define NC 20
#define CH 30                         // 2*4 + 2 + 20
#define CELLS (BATCHN * GS * GS)      // 6272
#define NTOT (CELLS * NB)             // 12544
#define NPOW 16384
#define PER_BATCH (GS * GS * NB)      // 98
#define THR_NMS 0.3f

typedef unsigned long long u64;

// ---------------- device scratch (static; no cudaMalloc) ---------------------
__device__ u64 g_keys[NTOT];
__device__ u64 g_sorted[NTOT];
__device__ float4 g_box[NTOT];
__device__ float g_score[NTOT];
__device__ unsigned char g_label[NTOT];
__device__ unsigned char g_keep[NTOT];

// sigmoid matching XLA-GPU exp-based logistic: 1/(1+__nv_expf(-x)), div.rn
__device__ __forceinline__ float sigmoidf(float x) {
    return 1.0f / (1.0f + expf(-x));
}

// float -> order-preserving uint32
__device__ __forceinline__ unsigned f2sortable(float f) {
    unsigned b = __float_as_uint(f);
    return (b & 0x80000000u) ? ~b : (b | 0x80000000u);
}

__device__ __forceinline__ void cs(u64& a, u64& b, bool dir) {
    if ((a < b) == dir) { u64 t = a; a = b; b = t; }
}

// ============ 1) fused decode + per-batch local sort + greedy NMS ============
__global__ void __launch_bounds__(128) decode_nms_kernel(const float* __restrict__ p) {
    __shared__ u64 s_key[128];
    __shared__ float4 s_box[PER_BATCH];
    __shared__ unsigned char s_lab[PER_BATCH];
    __shared__ unsigned char s_keep[PER_BATCH];
    __shared__ float4 s_nbox[PER_BATCH];
    __shared__ unsigned char s_nlab[PER_BATCH];
    __shared__ unsigned char s_nloc[PER_BATCH];
    __shared__ unsigned char s_sup[PER_BATCH];

    int tid = threadIdx.x;
    int b = blockIdx.x;

    if (tid < GS * GS) {
        int cell = b * (GS * GS) + tid;
        const float* q = p + (size_t)cell * CH;
        int gy = tid / GS;
        int gx = tid % GS;

        // argmax over sigmoid(cls) + 1 (first max wins)
        float best = sigmoidf(q[8 + NB + 0]);
        int bi = 0;
#pragma unroll
        for (int c = 1; c < NC; c++) {
            float v = sigmoidf(q[8 + NB + c]);
            if (v > best) { best = v; bi = c; }
        }
        unsigned char lab = (unsigned char)(bi + 1);

#pragma unroll
        for (int bb = 0; bb < NB; bb++) {
            int local = tid * NB + bb;
            int n = b * PER_BATCH + local;
            float conf = sigmoidf(q[8 + bb]);
            bool valid = conf > 0.5f;
            float sx = sigmoidf(q[bb * 4 + 0]);
            float sy = sigmoidf(q[bb * 4 + 1]);
            float w = q[bb * 4 + 2];
            float h = q[bb * 4 + 3];
            float cx = (sx + (float)gx) / 7.0f;
            float cy = (sy + (float)gy) / 7.0f;
            float4 bx;
            bx.x = cx - w / 2.0f;
            bx.y = cy - h / 2.0f;
            bx.z = cx + w / 2.0f;
            bx.w = cy + h / 2.0f;
            g_box[n] = bx;
            g_score[n] = conf;
            g_label[n] = lab;
            s_box[local] = bx;
            s_lab[local] = lab;
            s_keep[local] = 0;
            float keyf = valid ? conf : __int_as_float(0xff800000); // -inf
            u64 key = ((u64)f2sortable(keyf) << 32) | (unsigned)n;
            s_key[local] = key;
            g_keys[n] = key;
        }
    }
    if (tid >= PER_BATCH) s_key[tid] = 0ULL;   // pad sorts last
    __syncthreads();

    if (tid < 32) {
        // local bitonic sort of 128 keys, descending (same order as global sort
        // restricted to this batch: keys are unique)
        for (unsigned k = 2; k <= 128; k <<= 1) {
            for (unsigned j = k >> 1; j >= 1; j >>= 1) {
                for (int t2 = tid; t2 < 64; t2 += 32) {
                    int i = ((t2 & ~(j - 1)) << 1) | (t2 & (j - 1));
                    bool dir = ((i & k) == 0);
                    u64 a = s_key[i], bb2 = s_key[i | j];
                    if ((a < bb2) == dir) { s_key[i] = bb2; s_key[i | j] = a; }
                }
                __syncwarp();
            }
        }
        // count valid prefix (valid keys have top bit of high word set)
        int cnt = 0;
        for (int basei = 0; basei < 128; basei += 32) {
            u64 kk = s_key[basei + tid];
            bool v = ((unsigned)(kk >> 32)) >= 0x80000000u;
            unsigned m = __ballot_sync(0xffffffffu, v);
            cnt += __popc(m);
            if (m != 0xffffffffu) break;
        }
        // gather NMS working arrays
        for (int i = tid; i < cnt; i += 32) {
            unsigned idx = (unsigned)(s_key[i] & 0xffffffffu);
            int local = (int)(idx % PER_BATCH);
            s_nbox[i] = s_box[local];
            s_nlab[i] = s_lab[local];
            s_nloc[i] = (unsigned char)local;
            s_sup[i] = 0;
        }
        __syncwarp();

        // greedy NMS: serial over i, parallel over j
        for (int i = 0; i < cnt; i++) {
            if (s_sup[i]) continue;                  // uniform branch
            float4 bi = s_nbox[i];
            int li = s_nlab[i];
            float ai = (bi.z - bi.x) * (bi.w - bi.y);
            for (int j = i + 1 + tid; j < cnt; j += 32) {
                if (s_sup[j] || s_nlab[j] != li) continue;
                float4 bj = s_nbox[j];
                float ltx = fmaxf(bi.x, bj.x);
                float lty = fmaxf(bi.y, bj.y);
                float rbx = fminf(bi.z, bj.z);
                float rby = fminf(bi.w, bj.w);
                float iw = fmaxf(rbx - ltx, 0.0f);
                float ih = fmaxf(rby - lty, 0.0f);
                float inter = iw * ih;
                float aj = (bj.z - bj.x) * (bj.w - bj.y);
                float uni = ai + aj - inter;
                float iou = inter / fmaxf(uni, 1e-9f);
                if (iou > THR_NMS) s_sup[j] = 1;
            }
            __syncwarp();
        }
        for (int i = tid; i < cnt; i += 32)
            if (!s_sup[i]) s_keep[s_nloc[i]] = 1;
    }
    __syncthreads();
    if (tid < PER_BATCH) g_keep[b * PER_BATCH + tid] = s_keep[tid];
}

// ============ 2) global sort: register/warp/block hybrid bitonic =============
// Ownership: thread t owns 16 contiguous elements [16t,16t+16); warp w owns
// a 512-element region. j<=8 strides in registers, 16<=j<=256 warp-local,
// j>=512 block-global. Cross passes fused two strides per load.

__device__ __forceinline__ void reg_merge16(u64* sk, int base, int rot, bool dir) {
    u64 r[16];
#pragma unroll
    for (int ee = 0; ee < 16; ee++) { int e = (ee + rot) & 15; r[e] = sk[base + e]; }
#pragma unroll
    for (int j = 8; j >= 1; j >>= 1) {
#pragma unroll
        for (int e = 0; e < 16; e++) if (!(e & j)) cs(r[e], r[e | j], dir);
    }
#pragma unroll
    for (int ee = 0; ee < 16; ee++) { int e = (ee + rot) & 15; sk[base + e] = r[e]; }
    __syncwarp();
}

__device__ __forceinline__ void warp_pass(u64* sk, int wbase, int lane, int j, unsigned k) {
#pragma unroll 4
    for (int t2 = lane; t2 < 256; t2 += 32) {
        int i = wbase + (((t2 & ~(j - 1)) << 1) | (t2 & (j - 1)));
        bool dir = ((i & k) == 0);
        u64 a = sk[i], b = sk[i + j];
        if ((a < b) == dir) { sk[i] = b; sk[i + j] = a; }
    }
    __syncwarp();
}

__device__ __forceinline__ void warp_pass2(u64* sk, int wbase, int lane, int J, unsigned k) {
    int m = J >> 1;
#pragma unroll 4
    for (int t2 = lane; t2 < 128; t2 += 32) {
        int i = wbase + (((t2 & ~(m - 1)) << 2) | (t2 & (m - 1)));
        bool dir = ((i & k) == 0);
        u64 a = sk[i], b = sk[i + m], c = sk[i + J], d = sk[i + J + m];
        cs(a, c, dir); cs(b, d, dir); cs(a, b, dir); cs(c, d, dir);
        sk[i] = a; sk[i + m] = b; sk[i + J] = c; sk[i + J + m] = d;
    }
    __syncwarp();
}

__device__ __forceinline__ void glob_pass(u64* sk, int tid, int j, unsigned k) {
#pragma unroll 8
    for (int t2 = tid; t2 < (NPOW >> 1); t2 += 1024) {
        int i = ((t2 & ~(j - 1)) << 1) | (t2 & (j - 1));
        bool dir = ((i & k) == 0);
        u64 a = sk[i], b = sk[i + j];
        if ((a < b) == dir) { sk[i] = b; sk[i + j] = a; }
    }
    __syncthreads();
}

__device__ __forceinline__ void glob_pass2(u64* sk, int tid, int J, unsigned k) {
    int m = J >> 1;
#pragma unroll 4
    for (int t2 = tid; t2 < (NPOW >> 2); t2 += 1024) {
        int i = ((t2 & ~(m - 1)) << 2) | (t2 & (m - 1));
        bool dir = ((i & k) == 0);
        u64 a = sk[i], b = sk[i + m], c = sk[i + J], d = sk[i + J + m];
        cs(a, c, dir); cs(b, d, dir); cs(a, b, dir); cs(c, d, dir);
        sk[i] = a; sk[i + m] = b; sk[i + J] = c; sk[i + J + m] = d;
    }
    __syncthreads();
}

__device__ __forceinline__ void warp_chain(u64* sk, int wbase, int lane, int base,
                                           int rot, unsigned k) {
    // strides 256,128,64,32,16 then registers (j=8..1)
    warp_pass2(sk, wbase, lane, 256, k);
    warp_pass2(sk, wbase, lane, 64, k);
    warp_pass(sk, wbase, lane, 16, k);
    reg_merge16(sk, base, rot, ((unsigned)base & k) == 0);
}

__global__ void __launch_bounds__(1024, 1) sort_kernel() {
    extern __shared__ u64 sk[];
    int tid = threadIdx.x;
    int lane = tid & 31;
    int wbase = (tid >> 5) * 512;
    int base = tid * 16;
    int rot = tid & 15;

    for (int i = tid; i < NPOW; i += 1024)
        sk[i] = (i < NTOT) ? g_keys[i] : 0ULL;
    __syncthreads();

    // Phase A: k = 2..16 fully in registers
    {
        u64 r[16];
#pragma unroll
        for (int ee = 0; ee < 16; ee++) { int e = (ee + rot) & 15; r[e] = sk[base + e]; }
        // k=2
#pragma unroll
        for (int e = 0; e < 16; e += 2) cs(r[e], r[e + 1], (e & 2) == 0);
        // k=4: j=2,1
#pragma unroll
        for (int e = 0; e < 16; e++) if (!(e & 2)) cs(r[e], r[e + 2], (e & 4) == 0);
#pragma unroll
        for (int e = 0; e < 16; e += 2) cs(r[e], r[e + 1], (e & 4) == 0);
        // k=8: j=4,2,1
#pragma unroll
        for (int e = 0; e < 16; e++) if (!(e & 4)) cs(r[e], r[e + 4], (e & 8) == 0);
#pragma unroll
        for (int e = 0; e < 16; e++) if (!(e & 2)) cs(r[e], r[e + 2], (e & 8) == 0);
#pragma unroll
        for (int e = 0; e < 16; e += 2) cs(r[e], r[e + 1], (e & 8) == 0);
        // k=16: uniform direction within the thread's block
        bool d16 = ((base & 16) == 0);
#pragma unroll
        for (int j = 8; j >= 1; j >>= 1) {
#pragma unroll
            for (int e = 0; e < 16; e++) if (!(e & j)) cs(r[e], r[e | j], d16);
        }
#pragma unroll
        for (int ee = 0; ee < 16; ee++) { int e = (ee + rot) & 15; sk[base + e] = r[e]; }
    }
    __syncwarp();

    // Phase B: k = 32..512, entirely warp-local
    warp_pass(sk, wbase, lane, 16, 32);
    reg_merge16(sk, base, rot, (base & 32) == 0);

    warp_pass2(sk, wbase, lane, 32, 64);
    reg_merge16(sk, base, rot, (base & 64) == 0);

    warp_pass2(sk, wbase, lane, 64, 128);
    warp_pass(sk, wbase, lane, 16, 128);
    reg_merge16(sk, base, rot, (base & 128) == 0);

    warp_pass2(sk, wbase, lane, 128, 256);
    warp_pass2(sk, wbase, lane, 32, 256);
    reg_merge16(sk, base, rot, (base & 256) == 0);

    warp_pass2(sk, wbase, lane, 256, 512);
    warp_pass2(sk, wbase, lane, 64, 512);
    warp_pass(sk, wbase, lane, 16, 512);
    reg_merge16(sk, base, rot, (base & 512) == 0);

    __syncthreads();

    // Phase C: k = 1024..16384
    // k=1024
    glob_pass(sk, tid, 512, 1024);
    warp_chain(sk, wbase, lane, base, rot, 1024);
    __syncthreads();
    // k=2048
    glob_pass2(sk, tid, 1024, 2048);
    warp_chain(sk, wbase, lane, base, rot, 2048);
    __syncthreads();
    // k=4096
    glob_pass2(sk, tid, 2048, 4096);
    glob_pass(sk, tid, 512, 4096);
    warp_chain(sk, wbase, lane, base, rot, 4096);
    __syncthreads();
    // k=8192
    glob_pass2(sk, tid, 4096, 8192);
    glob_pass2(sk, tid, 1024, 8192);
    warp_chain(sk, wbase, lane, base, rot, 8192);
    __syncthreads();
    // k=16384
    glob_pass2(sk, tid, 8192, 16384);
    glob_pass2(sk, tid, 2048, 16384);
    glob_pass(sk, tid, 512, 16384);
    warp_chain(sk, wbase, lane, base, rot, 16384);
    __syncthreads();

    for (int i = tid; i < NTOT; i += 1024)
        g_sorted[i] = sk[i];
}

// ============ 3) write outputs through the sort permutation ==================
// layout: [ids (N)] [boxes (N,4)] [labels (N)] [scores (N)] [keep (N)]
__global__ void write_kernel(float* __restrict__ out) {
    int p = blockIdx.x * blockDim.x + threadIdx.x;
    if (p >= NTOT) return;
    unsigned idx = (unsigned)(g_sorted[p] & 0xffffffffu);
    out[p] = (float)(idx / PER_BATCH);
    float4 bx = g_box[idx];
    float* ob = out + NTOT + 4 * p;
    ob[0] = bx.x; ob[1] = bx.y; ob[2] = bx.z; ob[3] = bx.w;
    out[5 * NTOT + p] = (float)g_label[idx];
    out[6 * NTOT + p] = g_score[idx];
    out[7 * NTOT + p] = g_keep[idx] ? 1.0f : 0.0f;
}

// ---------------- launch -----------------------------------------------------
extern "C" void kernel_launch(void* const* d_in, const int* in_sizes, int n_in,
                              void* d_out, int out_size) {
    const float* p = (const float*)d_in[0];
    float* out = (float*)d_out;

    cudaFuncSetAttribute(sort_kernel,
                         cudaFuncAttributeMaxDynamicSharedMemorySize,
                         NPOW * (int)sizeof(u64));

    decode_nms_kernel<<<BATCHN, 128>>>(p);
    sort_kernel<<<1, 1024, NPOW * sizeof(u64)>>>();
    write_kernel<<<(NTOT + 255) / 256, 256>>>(out);
}

// round 4
// speedup vs baseline: 7.8088x; 6.7351x over previous
#include <cuda_runtime.h>
#include <cstdint>

// Problem constants
#define BATCHN 128
#define GS 7
#define NB 2
#define NC 20
#define CH 30
#define CELLS (BATCHN * GS * GS)      // 6272
#define NTOT (CELLS * NB)             // 12544
#define PER_BATCH (GS * GS * NB)      // 98
#define THR_NMS 0.3f

typedef unsigned long long u64;

// ---------------- device scratch (static; no cudaMalloc) ---------------------
__device__ u64 g_keys[NTOT];          // per-element key (sortable_score<<32 | idx)
__device__ u64 g_bvkeys[NTOT];        // per-batch sorted valid keys (prefix per batch)
__device__ u64 g_vkeys[NTOT];         // compacted valid keys (flat)
__device__ float4 g_box[NTOT];
__device__ float g_score[NTOT];
__device__ unsigned char g_label[NTOT];
__device__ unsigned char g_keep[NTOT];
__device__ int g_cnt[BATCHN];         // valid count per batch
__device__ u64 g_vmask[BATCHN * 2];   // validity bitmask per batch (98 bits)
__device__ int g_V;                   // total valid count
__device__ int g_invafter[BATCHN];    // invalid elements in batches > b

// sigmoid matching XLA-GPU exp-based logistic: 1/(1+__nv_expf(-x)), div.rn
__device__ __forceinline__ float sigmoidf(float x) {
    return 1.0f / (1.0f + expf(-x));
}

__device__ __forceinline__ unsigned f2sortable(float f) {
    unsigned b = __float_as_uint(f);
    return (b & 0x80000000u) ? ~b : (b | 0x80000000u);
}

// ============ 1) fused decode + per-batch local sort + greedy NMS ============
__global__ void __launch_bounds__(128) decode_nms_kernel(const float* __restrict__ p) {
    __shared__ float s_dec[GS * GS * CH];        // 1470 decoded values
    __shared__ u64 s_key[128];
    __shared__ float4 s_box[PER_BATCH];
    __shared__ unsigned char s_lab[PER_BATCH];
    __shared__ float4 s_nbox[PER_BATCH];
    __shared__ unsigned char s_nlab[PER_BATCH];
    __shared__ unsigned char s_nloc[PER_BATCH];
    __shared__ unsigned s_adj[PER_BATCH][4];     // suppression bitmask rows
    __shared__ unsigned s_supw[4];
    __shared__ unsigned s_wb[4];
    __shared__ int s_cnt;

    int tid = threadIdx.x;
    int b = blockIdx.x;

    // Phase 0: cooperative sigmoid decode (w,h channels raw)
    const float* pb = p + (size_t)b * (GS * GS * CH);
    for (int i = tid; i < GS * GS * CH; i += 128) {
        int c = i % CH;
        float x = pb[i];
        bool raw = (c == 2) | (c == 3) | (c == 6) | (c == 7);
        s_dec[i] = raw ? x : sigmoidf(x);
    }
    __syncthreads();

    // Phase 1: build boxes/labels/keys (one thread per box)
    bool valid = false;
    if (tid < PER_BATCH) {
        int cell = tid >> 1;
        int bb = tid & 1;
        int gy = cell / GS, gx = cell % GS;
        const float* d = s_dec + cell * CH;

        float best = d[8 + NB + 0];
        int bi = 0;
#pragma unroll
        for (int c = 1; c < NC; c++) {
            float v = d[8 + NB + c];
            if (v > best) { best = v; bi = c; }
        }
        unsigned char lab = (unsigned char)(bi + 1);

        float conf = d[8 + bb];
        valid = conf > 0.5f;
        float sx = d[bb * 4 + 0];
        float sy = d[bb * 4 + 1];
        float w = d[bb * 4 + 2];
        float h = d[bb * 4 + 3];
        float cx = (sx + (float)gx) / 7.0f;
        float cy = (sy + (float)gy) / 7.0f;
        float4 bx;
        bx.x = cx - w / 2.0f;
        bx.y = cy - h / 2.0f;
        bx.z = cx + w / 2.0f;
        bx.w = cy + h / 2.0f;

        int n = b * PER_BATCH + tid;
        g_box[n] = bx;
        g_score[n] = conf;
        g_label[n] = lab;
        g_keep[n] = 0;
        s_box[tid] = bx;
        s_lab[tid] = lab;
        float keyf = valid ? conf : __int_as_float(0xff800000);   // -inf
        u64 key = ((u64)f2sortable(keyf) << 32) | (unsigned)n;
        s_key[tid] = key;
        g_keys[n] = key;
    } else {
        s_key[tid] = 0ULL;
    }
    // validity ballot -> per-batch bitmask
    unsigned wb = __ballot_sync(0xffffffffu, valid);
    if ((tid & 31) == 0) s_wb[tid >> 5] = wb;
    __syncthreads();
    if (tid == 0) {
        u64 m0 = (u64)s_wb[0] | ((u64)s_wb[1] << 32);
        u64 m1 = (u64)s_wb[2] | ((u64)s_wb[3] << 32);
        g_vmask[2 * b] = m0;
        g_vmask[2 * b + 1] = m1;
        int cnt = __popcll(m0) + __popcll(m1);
        s_cnt = cnt;
        g_cnt[b] = cnt;
    }
    __syncthreads();

    // Phase 2: warp 0 bitonic-sorts the 128 keys descending
    if (tid < 32) {
        for (unsigned k = 2; k <= 128; k <<= 1) {
            for (unsigned j = k >> 1; j >= 1; j >>= 1) {
                for (int t2 = tid; t2 < 64; t2 += 32) {
                    int i = ((t2 & ~(j - 1)) << 1) | (t2 & (j - 1));
                    bool dir = ((i & k) == 0);
                    u64 a = s_key[i], bb2 = s_key[i | j];
                    if ((a < bb2) == dir) { s_key[i] = bb2; s_key[i | j] = a; }
                }
                __syncwarp();
            }
        }
    }
    __syncthreads();

    int cnt = s_cnt;

    // Phase 3: NMS working arrays + compacted sorted key export + adj zero
    for (int i = tid; i < cnt; i += 128) {
        u64 kk = s_key[i];
        unsigned idx = (unsigned)(kk & 0xffffffffu);
        int local = (int)(idx % PER_BATCH);
        s_nbox[i] = s_box[local];
        s_nlab[i] = s_lab[local];
        s_nloc[i] = (unsigned char)local;
        s_adj[i][0] = 0; s_adj[i][1] = 0; s_adj[i][2] = 0; s_adj[i][3] = 0;
        g_bvkeys[b * PER_BATCH + i] = kk;
    }
    __syncthreads();

    // Phase 4: fully-parallel pairwise IoU -> adjacency bits
    int P = cnt * (cnt - 1) / 2;
    for (int pp = tid; pp < P; pp += 128) {
        int s = P - 1 - pp;
        int k = (int)floorf((sqrtf(8.0f * (float)s + 1.0f) - 1.0f) * 0.5f);
        while ((k + 1) * (k + 2) / 2 <= s) k++;
        while (k * (k + 1) / 2 > s) k--;
        int o = s - k * (k + 1) / 2;
        int i = cnt - 2 - k;
        int j = cnt - 1 - o;
        if (s_nlab[i] == s_nlab[j]) {
            float4 bi = s_nbox[i];
            float4 bj = s_nbox[j];
            float ltx = fmaxf(bi.x, bj.x);
            float lty = fmaxf(bi.y, bj.y);
            float rbx = fminf(bi.z, bj.z);
            float rby = fminf(bi.w, bj.w);
            float iw = fmaxf(rbx - ltx, 0.0f);
            float ih = fmaxf(rby - lty, 0.0f);
            float inter = iw * ih;
            float ai = (bi.z - bi.x) * (bi.w - bi.y);
            float aj = (bj.z - bj.x) * (bj.w - bj.y);
            float uni = ai + aj - inter;
            float iou = inter / fmaxf(uni, 1e-9f);
            if (iou > THR_NMS)
                atomicOr(&s_adj[i][j >> 5], 1u << (j & 31));
        }
    }
    __syncthreads();

    // Phase 5: greedy scan over bitmask (single thread, register-resident)
    if (tid == 0) {
        unsigned sw0 = 0, sw1 = 0, sw2 = 0, sw3 = 0;
        for (int i = 0; i < cnt; i++) {
            unsigned mybit;
            switch (i >> 5) {
                case 0: mybit = (sw0 >> (i & 31)) & 1u; break;
                case 1: mybit = (sw1 >> (i & 31)) & 1u; break;
                case 2: mybit = (sw2 >> (i & 31)) & 1u; break;
                default: mybit = (sw3 >> (i & 31)) & 1u; break;
            }
            if (!mybit) {
                sw0 |= s_adj[i][0];
                sw1 |= s_adj[i][1];
                sw2 |= s_adj[i][2];
                sw3 |= s_adj[i][3];
            }
        }
        s_supw[0] = sw0; s_supw[1] = sw1; s_supw[2] = sw2; s_supw[3] = sw3;
    }
    __syncthreads();

    for (int i = tid; i < cnt; i += 128) {
        if (!((s_supw[i >> 5] >> (i & 31)) & 1u))
            g_keep[b * PER_BATCH + (int)s_nloc[i]] = 1;
    }
}

// ============ 2) scan counts + compact valid keys ============================
__global__ void __launch_bounds__(1024) scan_copy_kernel() {
    __shared__ int s_incl[BATCHN];
    __shared__ int s_cntv[BATCHN];
    __shared__ int s_wsum[4];
    int tid = threadIdx.x;
    int lane = tid & 31;

    int c = (tid < BATCHN) ? g_cnt[tid] : 0;
    if (tid < BATCHN) s_cntv[tid] = c;
    // warp inclusive scan (all warps execute; only first 4 matter)
    int x = c;
#pragma unroll
    for (int d = 1; d < 32; d <<= 1) {
        int y = __shfl_up_sync(0xffffffffu, x, d);
        if (lane >= d) x += y;
    }
    if (tid < BATCHN && lane == 31) s_wsum[tid >> 5] = x;
    __syncthreads();
    if (tid == 0) {
        int a = 0;
#pragma unroll
        for (int w = 0; w < 4; w++) { int t = s_wsum[w]; s_wsum[w] = a; a += t; }
    }
    __syncthreads();
    if (tid < BATCHN) s_incl[tid] = x + s_wsum[tid >> 5];
    __syncthreads();

    int V = s_incl[BATCHN - 1];
    if (tid == 0) g_V = V;
    if (tid < BATCHN)
        g_invafter[tid] = (NTOT - V) - (PER_BATCH * (tid + 1) - s_incl[tid]);

    // copy per-batch valid prefixes into flat array (warp per batch round-robin)
    int w = tid >> 5;
    for (int bb = w; bb < BATCHN; bb += 32) {
        int len = s_cntv[bb];
        int dst = s_incl[bb] - len;
        for (int i = lane; i < len; i += 32)
            g_vkeys[dst + i] = g_bvkeys[bb * PER_BATCH + i];
    }
}

// ============ 3) valid ranks: brute-force count over valid keys ==============
// 4 threads per element, bank-conflict-free rotated tile scan, dual accumulators
__global__ void __launch_bounds__(128) valid_rank_kernel(float* __restrict__ out) {
    __shared__ u64 tile[128];
    int tid = threadIdx.x;
    int V = g_V;
    int eBase = blockIdx.x * 32;
    if (eBase >= V) return;

    int e = eBase + (tid >> 2);
    int seg = tid & 3;
    int rot = seg * 4;
    bool active = (e < V);
    u64 mykey = active ? g_vkeys[e] : 0ULL;

    int c0 = 0, c1 = 0;
    int rounds = (V + 127) >> 7;
    for (int t = 0; t < rounds; t++) {
        int gi = t * 128 + tid;
        tile[tid] = (gi < V) ? g_vkeys[gi] : 0ULL;   // pad 0 < any valid key
        __syncthreads();
        if (active) {
#pragma unroll
            for (int kk = 0; kk < 32; kk += 2) {
                int i0 = seg * 32 + ((kk + rot) & 31);
                int i1 = seg * 32 + ((kk + 1 + rot) & 31);
                c0 += (tile[i0] > mykey);
                c1 += (tile[i1] > mykey);
            }
        }
        __syncthreads();
    }
    int rank = c0 + c1;
    rank += __shfl_xor_sync(0xffffffffu, rank, 1);
    rank += __shfl_xor_sync(0xffffffffu, rank, 2);

    if (active && seg == 0) {
        unsigned idx = (unsigned)(mykey & 0xffffffffu);
        out[rank] = (float)(idx / PER_BATCH);
        float4 bx = g_box[idx];
        float* ob = out + NTOT + 4 * rank;
        ob[0] = bx.x; ob[1] = bx.y; ob[2] = bx.z; ob[3] = bx.w;
        out[5 * NTOT + rank] = (float)g_label[idx];
        out[6 * NTOT + rank] = g_score[idx];
        out[7 * NTOT + rank] = g_keep[idx] ? 1.0f : 0.0f;
    }
}

// ============ 4) invalid ranks: O(1) per element =============================
__global__ void __launch_bounds__(128) invalid_write_kernel(float* __restrict__ out) {
    int n = blockIdx.x * 128 + threadIdx.x;
    if (n >= NTOT) return;
    u64 key = g_keys[n];
    if ((unsigned)(key >> 32) >= 0x80000000u) return;   // valid handled elsewhere

    int b = n / PER_BATCH;
    int local = n - b * PER_BATCH;
    u64 m0 = g_vmask[2 * b];
    u64 m1 = g_vmask[2 * b + 1];
    u64 i0 = ~m0;
    u64 i1 = (~m1) & ((1ULL << (PER_BATCH - 64)) - 1);  // 34 in-range bits
    int after;
    if (local < 64) {
        u64 hi = (local == 63) ? 0ULL : (i0 >> (local + 1));
        after = __popcll(hi) + __popcll(i1);
    } else {
        after = __popcll(i1 >> (local - 63));
    }
    int rank = g_V + g_invafter[b] + after;

    out[rank] = (float)b;
    float4 bx = g_box[n];
    float* ob = out + NTOT + 4 * rank;
    ob[0] = bx.x; ob[1] = bx.y; ob[2] = bx.z; ob[3] = bx.w;
    out[5 * NTOT + rank] = (float)g_label[n];
    out[6 * NTOT + rank] = g_score[n];
    out[7 * NTOT + rank] = 0.0f;
}

// ---------------- launch -----------------------------------------------------
extern "C" void kernel_launch(void* const* d_in, const int* in_sizes, int n_in,
                              void* d_out, int out_size) {
    const float* p = (const float*)d_in[0];
    float* out = (float*)d_out;

    decode_nms_kernel<<<BATCHN, 128>>>(p);
    scan_copy_kernel<<<1, 1024>>>();
    valid_rank_kernel<<<(NTOT * 4 + 127) / 128, 128>>>(out);
    invalid_write_kernel<<<(NTOT + 127) / 128, 128>>>(out);
}

// round 5
// speedup vs baseline: 7.8967x; 1.0113x over previous
#include <cuda_runtime.h>
#include <cstdint>

// Problem constants
#define BATCHN 128
#define GS 7
#define NB 2
#define NC 20
#define CH 30
#define CELLS (BATCHN * GS * GS)      // 6272
#define NTOT (CELLS * NB)             // 12544
#define PER_BATCH (GS * GS * NB)      // 98
#define THR_NMS 0.3f
#define NVB 784                       // valid-rank blocks (16 elems each, worst case)

typedef unsigned long long u64;

// ---------------- device scratch (static; no cudaMalloc) ---------------------
__device__ u64 g_vkeys[NTOT];         // compacted valid keys (any order)
__device__ float4 g_box[NTOT];
__device__ float4 g_pay[NTOT];        // (score, label, keep, 0)
__device__ int g_cnt[BATCHN];         // valid count per batch
__device__ u64 g_vmask[BATCHN * 2];   // validity bitmask per batch (98 bits)
__device__ int g_vtotal;              // atomic compaction counter (memset to 0)

// sigmoid matching XLA-GPU exp-based logistic: 1/(1+__nv_expf(-x)), div.rn
__device__ __forceinline__ float sigmoidf(float x) {
    return 1.0f / (1.0f + expf(-x));
}

__device__ __forceinline__ unsigned f2sortable(float f) {
    unsigned b = __float_as_uint(f);
    return (b & 0x80000000u) ? ~b : (b | 0x80000000u);
}

// ============ A) fused decode + per-batch sort + NMS + key compaction ========
__global__ void __launch_bounds__(128) decode_nms_kernel(const float* __restrict__ p) {
    __shared__ float s_dec[GS * GS * CH];        // 1470 decoded values
    __shared__ u64 s_key[128];
    __shared__ float4 s_box[PER_BATCH];
    __shared__ float s_score[PER_BATCH];
    __shared__ unsigned char s_lab[PER_BATCH];
    __shared__ unsigned char s_keep[PER_BATCH];
    __shared__ float4 s_nbox[PER_BATCH];
    __shared__ unsigned char s_nlab[PER_BATCH];
    __shared__ unsigned char s_nloc[PER_BATCH];
    __shared__ unsigned s_adj[PER_BATCH][4];     // suppression bitmask rows
    __shared__ unsigned s_supw[4];
    __shared__ unsigned s_wb[4];
    __shared__ int s_cnt;
    __shared__ int s_base;

    int tid = threadIdx.x;
    int b = blockIdx.x;

    // Phase 0: cooperative sigmoid decode (w,h channels raw)
    const float* pb = p + (size_t)b * (GS * GS * CH);
    for (int i = tid; i < GS * GS * CH; i += 128) {
        int c = i % CH;
        float x = pb[i];
        bool raw = (c == 2) | (c == 3) | (c == 6) | (c == 7);
        s_dec[i] = raw ? x : sigmoidf(x);
    }
    __syncthreads();

    // Phase 1: build boxes/labels/keys (one thread per box)
    bool valid = false;
    if (tid < PER_BATCH) {
        int cell = tid >> 1;
        int bb = tid & 1;
        int gy = cell / GS, gx = cell % GS;
        const float* d = s_dec + cell * CH;

        float best = d[8 + NB + 0];
        int bi = 0;
#pragma unroll
        for (int c = 1; c < NC; c++) {
            float v = d[8 + NB + c];
            if (v > best) { best = v; bi = c; }
        }
        unsigned char lab = (unsigned char)(bi + 1);

        float conf = d[8 + bb];
        valid = conf > 0.5f;
        float sx = d[bb * 4 + 0];
        float sy = d[bb * 4 + 1];
        float w = d[bb * 4 + 2];
        float h = d[bb * 4 + 3];
        float cx = (sx + (float)gx) / 7.0f;
        float cy = (sy + (float)gy) / 7.0f;
        float4 bx;
        bx.x = cx - w / 2.0f;
        bx.y = cy - h / 2.0f;
        bx.z = cx + w / 2.0f;
        bx.w = cy + h / 2.0f;

        int n = b * PER_BATCH + tid;
        g_box[n] = bx;
        s_box[tid] = bx;
        s_score[tid] = conf;
        s_lab[tid] = lab;
        s_keep[tid] = 0;
        float keyf = valid ? conf : __int_as_float(0xff800000);   // -inf
        s_key[tid] = ((u64)f2sortable(keyf) << 32) | (unsigned)n;
    } else {
        s_key[tid] = 0ULL;   // pad sorts last
    }
    unsigned wb = __ballot_sync(0xffffffffu, valid);
    if ((tid & 31) == 0) s_wb[tid >> 5] = wb;
    __syncthreads();
    if (tid == 0) {
        u64 m0 = (u64)s_wb[0] | ((u64)s_wb[1] << 32);
        u64 m1 = (u64)s_wb[2] | ((u64)s_wb[3] << 32);
        g_vmask[2 * b] = m0;
        g_vmask[2 * b + 1] = m1;
        int cnt = __popcll(m0) + __popcll(m1);
        s_cnt = cnt;
        g_cnt[b] = cnt;
        s_base = atomicAdd(&g_vtotal, cnt);
    }
    __syncthreads();

    // Phase 2: warp 0 bitonic-sorts the 128 keys descending
    if (tid < 32) {
        for (unsigned k = 2; k <= 128; k <<= 1) {
            for (unsigned j = k >> 1; j >= 1; j >>= 1) {
                for (int t2 = tid; t2 < 64; t2 += 32) {
                    int i = ((t2 & ~(j - 1)) << 1) | (t2 & (j - 1));
                    bool dir = ((i & k) == 0);
                    u64 a = s_key[i], bb2 = s_key[i | j];
                    if ((a < bb2) == dir) { s_key[i] = bb2; s_key[i | j] = a; }
                }
                __syncwarp();
            }
        }
    }
    __syncthreads();

    int cnt = s_cnt;
    int base = s_base;

    // Phase 3: NMS arrays + compacted key export + adjacency zero
    for (int i = tid; i < cnt; i += 128) {
        u64 kk = s_key[i];
        unsigned idx = (unsigned)(kk & 0xffffffffu);
        int local = (int)(idx % PER_BATCH);
        s_nbox[i] = s_box[local];
        s_nlab[i] = s_lab[local];
        s_nloc[i] = (unsigned char)local;
        s_adj[i][0] = 0; s_adj[i][1] = 0; s_adj[i][2] = 0; s_adj[i][3] = 0;
        g_vkeys[base + i] = kk;
    }
    __syncthreads();

    // Phase 4: parallel pairwise IoU -> adjacency bits (one j per thread per i)
    for (int i = 0; i < cnt - 1; i++) {
        int j = i + 1 + tid;
        if (j < cnt && s_nlab[i] == s_nlab[j]) {
            float4 bi = s_nbox[i];
            float4 bj = s_nbox[j];
            float ltx = fmaxf(bi.x, bj.x);
            float lty = fmaxf(bi.y, bj.y);
            float rbx = fminf(bi.z, bj.z);
            float rby = fminf(bi.w, bj.w);
            float iw = fmaxf(rbx - ltx, 0.0f);
            float ih = fmaxf(rby - lty, 0.0f);
            float inter = iw * ih;
            float ai = (bi.z - bi.x) * (bi.w - bi.y);
            float aj = (bj.z - bj.x) * (bj.w - bj.y);
            float uni = ai + aj - inter;
            float iou = inter / fmaxf(uni, 1e-9f);
            if (iou > THR_NMS)
                atomicOr(&s_adj[i][j >> 5], 1u << (j & 31));
        }
    }
    __syncthreads();

    // Phase 5: greedy scan over bitmask (single thread, register accumulators)
    if (tid == 0) {
        unsigned sw0 = 0, sw1 = 0, sw2 = 0, sw3 = 0;
        for (int i = 0; i < cnt; i++) {
            unsigned mybit;
            switch (i >> 5) {
                case 0: mybit = (sw0 >> (i & 31)) & 1u; break;
                case 1: mybit = (sw1 >> (i & 31)) & 1u; break;
                case 2: mybit = (sw2 >> (i & 31)) & 1u; break;
                default: mybit = (sw3 >> (i & 31)) & 1u; break;
            }
            if (!mybit) {
                sw0 |= s_adj[i][0];
                sw1 |= s_adj[i][1];
                sw2 |= s_adj[i][2];
                sw3 |= s_adj[i][3];
            }
        }
        s_supw[0] = sw0; s_supw[1] = sw1; s_supw[2] = sw2; s_supw[3] = sw3;
    }
    __syncthreads();

    for (int i = tid; i < cnt; i += 128) {
        if (!((s_supw[i >> 5] >> (i & 31)) & 1u))
            s_keep[s_nloc[i]] = 1;
    }
    __syncthreads();

    // Phase 6: payload write
    if (tid < PER_BATCH) {
        int n = b * PER_BATCH + tid;
        g_pay[n] = make_float4(s_score[tid], (float)s_lab[tid],
                               s_keep[tid] ? 1.0f : 0.0f, 0.0f);
    }
}

// ============ B) fused valid-rank + invalid-write ============================
// blocks [0, NVB): valid ranks (16 elems/block, 8 threads/elem, ull2 tiles)
// blocks [NVB, NVB+98): invalid elements, O(1) rank each (in-block count scan)
__global__ void __launch_bounds__(128) rank_write_kernel(float* __restrict__ out) {
    int blk = blockIdx.x;
    int tid = threadIdx.x;

    if (blk < NVB) {
        __shared__ ulonglong2 tile2[64];
        u64* tile = (u64*)tile2;
        int V = g_vtotal;
        int eBase = blk * 16;
        if (eBase >= V) return;

        int e = eBase + (tid >> 3);
        int seg = tid & 7;
        bool active = (e < V);
        u64 mykey = active ? g_vkeys[e] : 0ULL;

        int c0 = 0, c1 = 0;
        int rounds = (V + 127) >> 7;
        for (int t = 0; t < rounds; t++) {
            int gi = t * 128 + tid;
            tile[tid] = (gi < V) ? g_vkeys[gi] : 0ULL;  // pad 0 adds nothing
            __syncthreads();
            if (active) {
#pragma unroll
                for (int kk = 0; kk < 8; kk++) {
                    int i2 = seg * 8 + ((kk + seg) & 7);  // conflict-free rotation
                    ulonglong2 v = tile2[i2];
                    c0 += (v.x > mykey);
                    c1 += (v.y > mykey);
                }
            }
            __syncthreads();
        }
        int rank = c0 + c1;
        rank += __shfl_xor_sync(0xffffffffu, rank, 1);
        rank += __shfl_xor_sync(0xffffffffu, rank, 2);
        rank += __shfl_xor_sync(0xffffffffu, rank, 4);

        if (active && seg == 0) {
            unsigned idx = (unsigned)(mykey & 0xffffffffu);
            float4 bx = g_box[idx];
            float4 pay = g_pay[idx];
            out[rank] = (float)(idx / PER_BATCH);
            *(float4*)(out + NTOT + 4 * rank) = bx;
            out[5 * NTOT + rank] = pay.y;   // label
            out[6 * NTOT + rank] = pay.x;   // score
            out[7 * NTOT + rank] = pay.z;   // keep
        }
    } else {
        __shared__ int s_incl[BATCHN];
        __shared__ int s_ws[4];
        int lane = tid & 31;

        // in-block inclusive scan of g_cnt[0..127]
        int x = g_cnt[tid];
#pragma unroll
        for (int d = 1; d < 32; d <<= 1) {
            int y = __shfl_up_sync(0xffffffffu, x, d);
            if (lane >= d) x += y;
        }
        if (lane == 31) s_ws[tid >> 5] = x;
        __syncthreads();
        if (tid == 0) {
            int a = 0;
#pragma unroll
            for (int w = 0; w < 4; w++) { int t = s_ws[w]; s_ws[w] = a; a += t; }
        }
        __syncthreads();
        s_incl[tid] = x + s_ws[tid >> 5];
        __syncthreads();

        int V = s_incl[BATCHN - 1];
        int n = (blk - NVB) * 128 + tid;          // 98*128 == NTOT exactly
        int b = n / PER_BATCH;
        int local = n - b * PER_BATCH;
        u64 m0 = g_vmask[2 * b];
        u64 m1 = g_vmask[2 * b + 1];
        bool valid = (local < 64) ? ((m0 >> local) & 1ULL)
                                  : ((m1 >> (local - 64)) & 1ULL);
        if (valid) return;                        // handled by valid path

        u64 i0 = ~m0;
        u64 i1 = (~m1) & ((1ULL << (PER_BATCH - 64)) - 1);
        int after;
        if (local < 64) {
            u64 hi = (local == 63) ? 0ULL : (i0 >> (local + 1));
            after = __popcll(hi) + __popcll(i1);
        } else {
            after = __popcll(i1 >> (local - 63));
        }
        int invafter = (NTOT - V) - (PER_BATCH * (b + 1) - s_incl[b]);
        int rank = V + invafter + after;

        float4 bx = g_box[n];
        float4 pay = g_pay[n];
        out[rank] = (float)b;
        *(float4*)(out + NTOT + 4 * rank) = bx;
        out[5 * NTOT + rank] = pay.y;
        out[6 * NTOT + rank] = pay.x;
        out[7 * NTOT + rank] = 0.0f;
    }
}

// ---------------- launch -----------------------------------------------------
extern "C" void kernel_launch(void* const* d_in, const int* in_sizes, int n_in,
                              void* d_out, int out_size) {
    const float* p = (const float*)d_in[0];
    float* out = (float*)d_out;

    void* vt = nullptr;
    cudaGetSymbolAddress(&vt, g_vtotal);
    cudaMemsetAsync(vt, 0, sizeof(int));

    decode_nms_kernel<<<BATCHN, 128>>>(p);
    rank_write_kernel<<<NVB + (NTOT / 128), 128>>>(out);
}